// round 5
// baseline (speedup 1.0000x reference)
#include <cuda_runtime.h>
#include <cuda_bf16.h>
#include <math.h>

// ---------------- problem constants ----------------
#define GX 116
#define GY 87
#define BATCH 4
#define NSEG (BATCH * GX * GY)          // 40368
#define MAXN 1000000
#define C0 32
#define C1 128
#define EPSB 0.001f
#define PAD 68                           // floats per channel row (64 pts + pad)
#define TILE 64
#define NBLK 592

typedef unsigned long long ull;

// ---------------- scratch (__device__ globals; no allocation) ----------------
__device__ int      g_inv[MAXN];
__device__ int      g_rank[MAXN];
__device__ float4   g_feat[MAXN];        // segment-sorted packed features
__device__ int      g_sseg[MAXN];        // sorted segment id per point
__device__ int      g_cnt[NSEG];
__device__ int      g_off[NSEG];
__device__ unsigned g_h0min[NSEG * C0];
__device__ unsigned g_h0max[NSEG * C0];
__device__ unsigned g_amin[NSEG * C1];
__device__ unsigned g_amax[NSEG * C1];
__device__ float    g_asum[NSEG * C1];
__device__ float    g_m0[NSEG * C0];
__device__ float    g_min1[NSEG * C1];
__device__ float    g_max1[NSEG * C1];
__device__ double   g_mom[14];
__device__ double   g_s1[C1];
__device__ double   g_ss1[C1];
__device__ float    g_a0[C0], g_c0[C0];
__device__ float    g_a1[C1], g_c1[C1];
__device__ float    g_dense[BATCH * C1 * GY * GX];

// ---------------- helpers ----------------
__device__ __forceinline__ float swishf(float x) {
    return __fdividef(x, 1.0f + __expf(-x));
}
__device__ __forceinline__ float swish_seg_max(float pmin, float pmax, float a, float c) {
    return fmaxf(swishf(a * pmin + c), swishf(a * pmax + c));
}
__device__ __forceinline__ unsigned encf(float x) {
    unsigned u = __float_as_uint(x);
    return (u & 0x80000000u) ? ~u : (u | 0x80000000u);
}
__device__ __forceinline__ float decf(unsigned e) {
    unsigned u = (e & 0x80000000u) ? (e & 0x7FFFFFFFu) : ~e;
    return __uint_as_float(u);
}
__device__ __forceinline__ ull pk2(float lo, float hi) {
    ull r; asm("mov.b64 %0, {%1,%2};" : "=l"(r) : "f"(lo), "f"(hi)); return r;
}
__device__ __forceinline__ void upk2(ull v, float& lo, float& hi) {
    asm("mov.b64 {%0,%1}, %2;" : "=f"(lo), "=f"(hi) : "l"(v));
}
__device__ __forceinline__ ull fma2(ull a, ull b, ull c) {
    ull d; asm("fma.rn.f32x2 %0, %1, %2, %3;" : "=l"(d) : "l"(a), "l"(b), "l"(c)); return d;
}

template<int J>
__device__ __forceinline__ void bloop(unsigned base, const ull (&wp)[32], ull& acc01, ull& acc23) {
    if constexpr (J < 32) {
        ull h01, h23;
        asm volatile("ld.shared.v2.u64 {%0,%1}, [%2+%3];"
                     : "=l"(h01), "=l"(h23) : "r"(base), "n"(J * PAD * 4));
        acc01 = fma2(h01, wp[J], acc01);
        acc23 = fma2(h23, wp[J], acc23);
        bloop<J + 1>(base, wp, acc01, acc23);
    }
}

// ---------------- init ----------------
__global__ void k_init() {
    int i = blockIdx.x * blockDim.x + threadIdx.x;
    if (i < NSEG * C1) { g_amin[i] = 0xFFFFFFFFu; g_amax[i] = 0u; g_asum[i] = 0.0f; }
    if (i < NSEG * C0) { g_h0min[i] = 0xFFFFFFFFu; g_h0max[i] = 0u; }
    if (i < NSEG) g_cnt[i] = 0;
    if (i < 14)   g_mom[i] = 0.0;
    if (i < C1)   { g_s1[i] = 0.0; g_ss1[i] = 0.0; }
}

// ---------------- P1: inv, rank, histogram, feature moments ----------------
__global__ void k_p1(const float* __restrict__ pts, int N) {
    __shared__ double smom[14];
    if (threadIdx.x < 14) smom[threadIdx.x] = 0.0;
    __syncthreads();

    int i = blockIdx.x * blockDim.x + threadIdx.x;
    float m[14];
#pragma unroll
    for (int k = 0; k < 14; k++) m[k] = 0.0f;

    if (i < N) {
        const float* p = pts + (size_t)i * 5;
        float b = p[0], x = p[1], y = p[2], t = p[3], pol = p[4];
        int cx = (int)floorf(x / 3.0f);
        int cy = (int)floorf(y / 3.0f);
        int bi = (int)b;
        int inv = (bi * GX + cx) * GY + cy;
        g_inv[i] = inv;
        g_rank[i] = atomicAdd(&g_cnt[inv], 1);
        float f0 = x / 346.0f, f1 = y / 260.0f, f2 = t / 200.0f, f3 = pol;
        m[0] = f0; m[1] = f1; m[2] = f2; m[3] = f3;
        m[4] = f0 * f0; m[5] = f0 * f1; m[6] = f0 * f2; m[7] = f0 * f3;
        m[8] = f1 * f1; m[9] = f1 * f2; m[10] = f1 * f3;
        m[11] = f2 * f2; m[12] = f2 * f3; m[13] = f3 * f3;
    }

#pragma unroll
    for (int k = 0; k < 14; k++) {
#pragma unroll
        for (int off = 16; off > 0; off >>= 1)
            m[k] += __shfl_down_sync(0xFFFFFFFFu, m[k], off);
    }
    if ((threadIdx.x & 31) == 0) {
#pragma unroll
        for (int k = 0; k < 14; k++) atomicAdd(&smom[k], (double)m[k]);
    }
    __syncthreads();
    if (threadIdx.x < 14) atomicAdd(&g_mom[threadIdx.x], smom[threadIdx.x]);
}

// ---------------- scan ----------------
__global__ void k_scan() {
    __shared__ int partial[1024];
    const int PER = (NSEG + 1023) / 1024;
    int tid = threadIdx.x;
    int base = tid * PER;
    int s = 0;
    for (int k = 0; k < PER; k++) {
        int idx = base + k;
        if (idx < NSEG) s += g_cnt[idx];
    }
    partial[tid] = s;
    __syncthreads();
    for (int d = 1; d < 1024; d <<= 1) {
        int v = partial[tid];
        int add = (tid >= d) ? partial[tid - d] : 0;
        __syncthreads();
        partial[tid] = v + add;
        __syncthreads();
    }
    int run = (tid == 0) ? 0 : partial[tid - 1];
    for (int k = 0; k < PER; k++) {
        int idx = base + k;
        if (idx < NSEG) {
            g_off[idx] = run;
            run += g_cnt[idx];
        }
    }
}

// ---------------- S0: bn0 affine from moments ----------------
__global__ void k_s0(const float* __restrict__ W0, const float* __restrict__ g0,
                     const float* __restrict__ b0, int N) {
    int ch = threadIdx.x;
    if (ch >= C0) return;
    double s0 = g_mom[0], s1 = g_mom[1], s2 = g_mom[2], s3 = g_mom[3];
    double M00 = g_mom[4], M01 = g_mom[5], M02 = g_mom[6], M03 = g_mom[7];
    double M11 = g_mom[8], M12 = g_mom[9], M13 = g_mom[10];
    double M22 = g_mom[11], M23 = g_mom[12], M33 = g_mom[13];
    double w0 = W0[ch], w1 = W0[C0 + ch], w2 = W0[2 * C0 + ch], w3 = W0[3 * C0 + ch];
    double dN = (double)N;
    double mu = (s0 * w0 + s1 * w1 + s2 * w2 + s3 * w3) / dN;
    double ex2 = (M00 * w0 * w0 + M11 * w1 * w1 + M22 * w2 * w2 + M33 * w3 * w3
                  + 2.0 * (M01 * w0 * w1 + M02 * w0 * w2 + M03 * w0 * w3
                           + M12 * w1 * w2 + M13 * w1 * w3 + M23 * w2 * w3)) / dN;
    double var = ex2 - mu * mu;
    double a = (double)g0[ch] / sqrt(var + (double)EPSB);
    g_a0[ch] = (float)a;
    g_c0[ch] = (float)((double)b0[ch] - mu * a);
}

// ---------------- scatter (no atomics: off + rank) ----------------
__global__ void k_scatter(const float* __restrict__ pts, int N) {
    int i = blockIdx.x * blockDim.x + threadIdx.x;
    if (i >= N) return;
    const float* p = pts + (size_t)i * 5;
    float x = p[1], y = p[2], t = p[3], pol = p[4];
    int inv = g_inv[i];
    int pos = g_off[inv] + g_rank[i];
    g_feat[pos] = make_float4(x / 346.0f, y / 260.0f, t / 200.0f, pol);
    g_sseg[pos] = inv;
}

// ---------------- streaming point pass ----------------
__global__ void __launch_bounds__(128)
k_seg(const float* __restrict__ W0, const float* __restrict__ W1, int N) {
    int tid = threadIdx.x, c = tid & 31, row = tid >> 5;

    ull wp[32];
#pragma unroll
    for (int j = 0; j < 32; j++) {
        float v = W1[j * C1 + tid];
        wp[j] = pk2(v, v);
    }
    float w00 = W0[c], w01 = W0[C0 + c], w02 = W0[2 * C0 + c], w03 = W0[3 * C0 + c];
    float a0 = g_a0[c], c0 = g_c0[c];

    __shared__ __align__(16) float h0s[C0 * PAD];
    __shared__ __align__(16) int ss[TILE];
    unsigned h0base = (unsigned)__cvta_generic_to_shared(h0s);

    int Ttot = (N + TILE - 1) / TILE;
    int t0 = (int)((long long)blockIdx.x * Ttot / gridDim.x);
    int t1 = (int)((long long)(blockIdx.x + 1) * Ttot / gridDim.x);

    // phase A running state (per thread: channel c over its strided points)
    int curA = -1; float lmin = 0.0f, lmax = 0.0f;
    // phase B running state (per thread: out channel tid)
    int curB = -1; float rmin = 0.0f, rmax = 0.0f, rsum = 0.0f;
    double dsum = 0.0, dssq = 0.0;

    for (int tt = t0; tt < t1; tt++) {
        int pbase = tt * TILE;
        int m = min(TILE, N - pbase);
        // ---- phase A ----
        for (int p = row; p < TILE; p += 4) {
            if (p < m) {
                int sg = g_sseg[pbase + p];
                float4 f = g_feat[pbase + p];
                float h = f.x * w00 + f.y * w01 + f.z * w02 + f.w * w03;
                if (sg != curA) {
                    if (curA >= 0) {
                        atomicMin(&g_h0min[curA * C0 + c], encf(lmin));
                        atomicMax(&g_h0max[curA * C0 + c], encf(lmax));
                    }
                    curA = sg; lmin = h; lmax = h;
                } else {
                    lmin = fminf(lmin, h);
                    lmax = fmaxf(lmax, h);
                }
                h0s[c * PAD + p] = swishf(a0 * h + c0);
                if (c == 0) ss[p] = sg;
            } else {
                h0s[c * PAD + p] = 0.0f;
                if (c == 0) ss[p] = -1;
            }
        }
        __syncthreads();
        // ---- phase B ----
        ull tssq = 0;
        float tsum = 0.0f, sssq = 0.0f;
        const int4* ss4 = (const int4*)ss;
        for (int g4 = 0; g4 < TILE / 4; g4++) {
            int4 s = ss4[g4];
            ull acc01 = 0, acc23 = 0;
            unsigned base = h0base + g4 * 16;
            bloop<0>(base, wp, acc01, acc23);
            float A0, A1, A2, A3;
            upk2(acc01, A0, A1);
            upk2(acc23, A2, A3);
            if (s.x == s.w && s.x >= 0) {      // sorted => uniform group
                if (s.x != curB) {
                    if (curB >= 0) {
                        size_t ix = (size_t)curB * C1 + tid;
                        atomicMin(&g_amin[ix], encf(rmin));
                        atomicMax(&g_amax[ix], encf(rmax));
                        atomicAdd(&g_asum[ix], rsum);
                    }
                    curB = s.x; rmin = INFINITY; rmax = -INFINITY; rsum = 0.0f;
                }
                rmin = fminf(rmin, fminf(fminf(A0, A1), fminf(A2, A3)));
                rmax = fmaxf(rmax, fmaxf(fmaxf(A0, A1), fmaxf(A2, A3)));
                float gs = (A0 + A1) + (A2 + A3);
                rsum += gs;
                tsum += gs;
                tssq = fma2(acc01, acc01, tssq);
                tssq = fma2(acc23, acc23, tssq);
            } else {
                float av[4] = {A0, A1, A2, A3};
                int sv[4] = {s.x, s.y, s.z, s.w};
#pragma unroll
                for (int k = 0; k < 4; k++) {
                    if (sv[k] < 0) continue;
                    if (sv[k] != curB) {
                        if (curB >= 0) {
                            size_t ix = (size_t)curB * C1 + tid;
                            atomicMin(&g_amin[ix], encf(rmin));
                            atomicMax(&g_amax[ix], encf(rmax));
                            atomicAdd(&g_asum[ix], rsum);
                        }
                        curB = sv[k]; rmin = av[k]; rmax = av[k]; rsum = av[k];
                    } else {
                        rmin = fminf(rmin, av[k]);
                        rmax = fmaxf(rmax, av[k]);
                        rsum += av[k];
                    }
                    tsum += av[k];
                    sssq = fmaf(av[k], av[k], sssq);
                }
            }
        }
        float q0, q1;
        upk2(tssq, q0, q1);
        dsum += (double)tsum;
        dssq += (double)(q0 + q1 + sssq);
        __syncthreads();
    }

    // final flushes
    if (curA >= 0) {
        atomicMin(&g_h0min[curA * C0 + c], encf(lmin));
        atomicMax(&g_h0max[curA * C0 + c], encf(lmax));
    }
    if (curB >= 0) {
        size_t ix = (size_t)curB * C1 + tid;
        atomicMin(&g_amin[ix], encf(rmin));
        atomicMax(&g_amax[ix], encf(rmax));
        atomicAdd(&g_asum[ix], rsum);
    }
    atomicAdd(&g_s1[tid], dsum);
    atomicAdd(&g_ss1[tid], dssq);
}

// ---------------- m0 per (seg, in-channel) ----------------
__global__ void k_m0() {
    int i = blockIdx.x * blockDim.x + threadIdx.x;
    if (i >= NSEG * C0) return;
    int seg = i >> 5, ch = i & 31;
    float v = 0.0f;
    if (g_cnt[seg] > 0) {
        float mn = decf(g_h0min[i]);
        float mx = decf(g_h0max[i]);
        v = swish_seg_max(mn, mx, g_a0[ch], g_c0[ch]);
    }
    g_m0[i] = v;
}

// ---------------- finalize per segment: B, m1 endpoints, BN1 corrections ----------------
__global__ void __launch_bounds__(128)
k_fin(const float* __restrict__ W1) {
    int tid = threadIdx.x;
    float whi[32];
#pragma unroll
    for (int j = 0; j < 32; j++) whi[j] = W1[(32 + j) * C1 + tid];

    __shared__ float m0s[32];
    double dsum = 0.0, dssq = 0.0;

    for (int seg = blockIdx.x; seg < NSEG; seg += gridDim.x) {
        int cnt = g_cnt[seg];           // uniform across block
        if (cnt == 0) continue;
        if (tid < 32) m0s[tid] = g_m0[seg * C0 + tid];
        __syncthreads();
        float B = 0.0f;
#pragma unroll
        for (int j = 0; j < 32; j++) B = fmaf(m0s[j], whi[j], B);
        size_t ix = (size_t)seg * C1 + tid;
        float amin = decf(g_amin[ix]);
        float amax = decf(g_amax[ix]);
        float as = g_asum[ix];
        g_min1[ix] = amin + B;
        g_max1[ix] = amax + B;
        float fc = (float)cnt;
        dsum += (double)(fc * B);
        dssq += (double)(2.0f * B * as + fc * B * B);
        __syncthreads();
    }
    atomicAdd(&g_s1[tid], dsum);
    atomicAdd(&g_ss1[tid], dssq);
}

// ---------------- S1: bn1 affine ----------------
__global__ void k_s1(const float* __restrict__ g1, const float* __restrict__ b1, int N) {
    int ch = threadIdx.x;
    if (ch >= C1) return;
    double dN = (double)N;
    double mu = g_s1[ch] / dN;
    double var = g_ss1[ch] / dN - mu * mu;
    double a = (double)g1[ch] / sqrt(var + (double)EPSB);
    g_a1[ch] = (float)a;
    g_c1[ch] = (float)((double)b1[ch] - mu * a);
}

// ---------------- T2: resolve m1, scatter into dense ----------------
__global__ void k_t2() {
    int i = blockIdx.x * blockDim.x + threadIdx.x;
    if (i >= NSEG * C1) return;
    int ch = i & (C1 - 1);
    int seg = i >> 7;
    float val = 0.0f;
    if (g_cnt[seg] > 0) {
        float a = g_a1[ch], c = g_c1[ch];
        float pmin = g_min1[i], pmax = g_max1[i];
        val = fmaxf(swishf(a * pmin + c), swishf(a * pmax + c));
    }
    int cy = seg % GY;
    int r = seg / GY;
    int cx = r % GX;
    int b = r / GX;
    g_dense[((b * C1 + ch) * GY + cy) * GX + cx] = val;
}

// ---------------- R: bilinear resize ----------------
__global__ void k_resize(float* __restrict__ out, int total) {
    int i = blockIdx.x * blockDim.x + threadIdx.x;
    if (i >= total) return;
    int xo = i % 224;
    int yo = (i / 224) % 224;
    int bc = i / (224 * 224);

    const float sy = (GY - 1.0f) / 223.0f;
    const float sx = (GX - 1.0f) / 223.0f;
    float yy = (float)yo * sy;
    float xx = (float)xo * sx;
    int y0 = (int)floorf(yy);
    int x0 = (int)floorf(xx);
    int y1 = min(y0 + 1, GY - 1);
    int x1 = min(x0 + 1, GX - 1);
    float wy = yy - (float)y0;
    float wx = xx - (float)x0;

    const float* d = g_dense + (size_t)bc * GY * GX;
    float d00 = d[y0 * GX + x0];
    float d01 = d[y0 * GX + x1];
    float d10 = d[y1 * GX + x0];
    float d11 = d[y1 * GX + x1];
    float xh0 = d00 * (1.0f - wy) + d10 * wy;
    float xh1 = d01 * (1.0f - wy) + d11 * wy;
    out[i] = xh0 * (1.0f - wx) + xh1 * wx;
}

// ---------------- launch ----------------
extern "C" void kernel_launch(void* const* d_in, const int* in_sizes, int n_in,
                              void* d_out, int out_size) {
    const float* pts = (const float*)d_in[1];
    const float* W0  = (const float*)d_in[2];
    const float* g0  = (const float*)d_in[3];
    const float* b0  = (const float*)d_in[4];
    const float* W1  = (const float*)d_in[5];
    const float* g1  = (const float*)d_in[6];
    const float* b1  = (const float*)d_in[7];
    float* out = (float*)d_out;
    int N = in_sizes[1] / 5;
    if (N > MAXN) N = MAXN;

    k_init<<<(NSEG * C1 + 255) / 256, 256>>>();
    k_p1<<<(N + 255) / 256, 256>>>(pts, N);
    k_scan<<<1, 1024>>>();
    k_s0<<<1, 32>>>(W0, g0, b0, N);
    k_scatter<<<(N + 255) / 256, 256>>>(pts, N);
    k_seg<<<NBLK, 128>>>(W0, W1, N);
    k_m0<<<(NSEG * C0 + 255) / 256, 256>>>();
    k_fin<<<NBLK, 128>>>(W1);
    k_s1<<<1, C1>>>(g1, b1, N);
    k_t2<<<(NSEG * C1 + 255) / 256, 256>>>();
    k_resize<<<(out_size + 255) / 256, 256>>>(out, out_size);
}

// round 6
// speedup vs baseline: 1.2255x; 1.2255x over previous
#include <cuda_runtime.h>
#include <cuda_bf16.h>
#include <math.h>

// ---------------- problem constants ----------------
#define GX 116
#define GY 87
#define BATCH 4
#define NSEG (BATCH * GX * GY)          // 40368
#define MAXN 1000000
#define C0 32
#define C1 128
#define EPSB 0.001f
#define PAD 68                           // floats per channel row (64 pts + pad)
#define NBLK 592

typedef unsigned long long ull;

// ---------------- scratch (__device__ globals; no allocation) ----------------
__device__ int    g_inv[MAXN];
__device__ int    g_rank[MAXN];
__device__ float4 g_feat[MAXN];          // segment-sorted packed features
__device__ int    g_cnt[NSEG];
__device__ int    g_off[NSEG];
__device__ float  g_min1[NSEG * C1];
__device__ float  g_max1[NSEG * C1];
__device__ double g_mom[14];             // Σf (4) + Σ f f^T upper (10)
__device__ double g_s1[C1];
__device__ double g_ss1[C1];
__device__ float  g_a0[C0], g_c0[C0];    // bn0 affine: a*x + c
__device__ float  g_a1[C1], g_c1[C1];
__device__ float  g_dense[BATCH * C1 * GY * GX];

// ---------------- helpers ----------------
__device__ __forceinline__ float swishf(float x) {
    return __fdividef(x, 1.0f + __expf(-x));
}
__device__ __forceinline__ float swish_seg_max(float pmin, float pmax, float a, float c) {
    float lo = a * pmin + c;
    float hi = a * pmax + c;
    return fmaxf(swishf(lo), swishf(hi));
}
__device__ __forceinline__ ull pk2(float lo, float hi) {
    ull r; asm("mov.b64 %0, {%1,%2};" : "=l"(r) : "f"(lo), "f"(hi)); return r;
}
__device__ __forceinline__ void upk2(ull v, float& lo, float& hi) {
    asm("mov.b64 {%0,%1}, %2;" : "=f"(lo), "=f"(hi) : "l"(v));
}
__device__ __forceinline__ ull fma2(ull a, ull b, ull c) {
    ull d; asm("fma.rn.f32x2 %0, %1, %2, %3;" : "=l"(d) : "l"(a), "l"(b), "l"(c)); return d;
}
__device__ __forceinline__ ull add2(ull a, ull b) {
    ull d; asm("add.rn.f32x2 %0, %1, %2;" : "=l"(d) : "l"(a), "l"(b)); return d;
}

// unrolled f32x2 dot over 32 channels; smem laid out channel-major (stride PAD floats)
template<int J>
__device__ __forceinline__ void bloop(unsigned base, const ull (&wp)[32], ull& acc01, ull& acc23) {
    if constexpr (J < 32) {
        ull h01, h23;
        asm volatile("ld.shared.v2.u64 {%0,%1}, [%2+%3];"
                     : "=l"(h01), "=l"(h23) : "r"(base), "n"(J * PAD * 4));
        acc01 = fma2(h01, wp[J], acc01);
        acc23 = fma2(h23, wp[J], acc23);
        bloop<J + 1>(base, wp, acc01, acc23);
    }
}

// ---------------- init ----------------
__global__ void k_init() {
    int i = blockIdx.x * blockDim.x + threadIdx.x;
    if (i < NSEG) g_cnt[i] = 0;
    if (i < 14)   g_mom[i] = 0.0;
    if (i < C1)   { g_s1[i] = 0.0; g_ss1[i] = 0.0; }
}

// ---------------- P1: inv, rank, histogram, feature moments ----------------
__global__ void k_p1(const float* __restrict__ pts, int N) {
    __shared__ double smom[14];
    if (threadIdx.x < 14) smom[threadIdx.x] = 0.0;
    __syncthreads();

    int i = blockIdx.x * blockDim.x + threadIdx.x;
    float m[14];
#pragma unroll
    for (int k = 0; k < 14; k++) m[k] = 0.0f;

    if (i < N) {
        const float* p = pts + (size_t)i * 5;
        float b = p[0], x = p[1], y = p[2], t = p[3], pol = p[4];
        int cx = (int)floorf(x / 3.0f);
        int cy = (int)floorf(y / 3.0f);
        int bi = (int)b;
        int inv = (bi * GX + cx) * GY + cy;
        g_inv[i] = inv;
        g_rank[i] = atomicAdd(&g_cnt[inv], 1);
        float f0 = x / 346.0f, f1 = y / 260.0f, f2 = t / 200.0f, f3 = pol;
        m[0] = f0; m[1] = f1; m[2] = f2; m[3] = f3;
        m[4] = f0 * f0; m[5] = f0 * f1; m[6] = f0 * f2; m[7] = f0 * f3;
        m[8] = f1 * f1; m[9] = f1 * f2; m[10] = f1 * f3;
        m[11] = f2 * f2; m[12] = f2 * f3; m[13] = f3 * f3;
    }

#pragma unroll
    for (int k = 0; k < 14; k++) {
#pragma unroll
        for (int off = 16; off > 0; off >>= 1)
            m[k] += __shfl_down_sync(0xFFFFFFFFu, m[k], off);
    }
    if ((threadIdx.x & 31) == 0) {
#pragma unroll
        for (int k = 0; k < 14; k++) atomicAdd(&smom[k], (double)m[k]);
    }
    __syncthreads();
    if (threadIdx.x < 14) atomicAdd(&g_mom[threadIdx.x], smom[threadIdx.x]);
}

// ---------------- scan: exclusive prefix of counts (single block) ----------------
__global__ void k_scan() {
    __shared__ int partial[1024];
    const int PER = (NSEG + 1023) / 1024;
    int tid = threadIdx.x;
    int base = tid * PER;
    int s = 0;
    for (int k = 0; k < PER; k++) {
        int idx = base + k;
        if (idx < NSEG) s += g_cnt[idx];
    }
    partial[tid] = s;
    __syncthreads();
    for (int d = 1; d < 1024; d <<= 1) {
        int v = partial[tid];
        int add = (tid >= d) ? partial[tid - d] : 0;
        __syncthreads();
        partial[tid] = v + add;
        __syncthreads();
    }
    int run = (tid == 0) ? 0 : partial[tid - 1];
    for (int k = 0; k < PER; k++) {
        int idx = base + k;
        if (idx < NSEG) {
            g_off[idx] = run;
            run += g_cnt[idx];
        }
    }
}

// ---------------- S0: bn0 affine from moments ----------------
__global__ void k_s0(const float* __restrict__ W0, const float* __restrict__ g0,
                     const float* __restrict__ b0, int N) {
    int ch = threadIdx.x;
    if (ch >= C0) return;
    double s0 = g_mom[0], s1 = g_mom[1], s2 = g_mom[2], s3 = g_mom[3];
    double M00 = g_mom[4], M01 = g_mom[5], M02 = g_mom[6], M03 = g_mom[7];
    double M11 = g_mom[8], M12 = g_mom[9], M13 = g_mom[10];
    double M22 = g_mom[11], M23 = g_mom[12], M33 = g_mom[13];
    double w0 = W0[ch], w1 = W0[C0 + ch], w2 = W0[2 * C0 + ch], w3 = W0[3 * C0 + ch];
    double dN = (double)N;
    double mu = (s0 * w0 + s1 * w1 + s2 * w2 + s3 * w3) / dN;
    double ex2 = (M00 * w0 * w0 + M11 * w1 * w1 + M22 * w2 * w2 + M33 * w3 * w3
                  + 2.0 * (M01 * w0 * w1 + M02 * w0 * w2 + M03 * w0 * w3
                           + M12 * w1 * w2 + M13 * w1 * w3 + M23 * w2 * w3)) / dN;
    double var = ex2 - mu * mu;
    double a = (double)g0[ch] / sqrt(var + (double)EPSB);
    g_a0[ch] = (float)a;
    g_c0[ch] = (float)((double)b0[ch] - mu * a);
}

// ---------------- scatter (no atomics: off + rank) ----------------
__global__ void k_scatter(const float* __restrict__ pts, int N) {
    int i = blockIdx.x * blockDim.x + threadIdx.x;
    if (i >= N) return;
    const float* p = pts + (size_t)i * 5;
    float x = p[1], y = p[2], t = p[3], pol = p[4];
    int inv = g_inv[i];
    int pos = g_off[inv] + g_rank[i];
    g_feat[pos] = make_float4(x / 346.0f, y / 260.0f, t / 200.0f, pol);
}

// ---------------- per-segment reduction: persistent blocks ----------------
__global__ void __launch_bounds__(C1, 4)
k_seg(const float* __restrict__ W0, const float* __restrict__ W1) {
    int tid = threadIdx.x;          // output channel 0..127
    int c   = tid & 31;             // input channel for phase A
    int row = tid >> 5;             // warp row 0..3

    __shared__ __align__(16) float h0s[C0 * PAD];
    __shared__ float whis[32 * C1];           // W1[32:64,:] for epilogue
    __shared__ float pm[4][32], pM[4][32];
    __shared__ float m0s[32];

    // packed W1[:32, tid] in registers
    ull wp[32];
#pragma unroll
    for (int j = 0; j < 32; j++) {
        float v = W1[j * C1 + tid];
        wp[j] = pk2(v, v);
    }
    // W1[32:64, :] into shared (coalesced, once per block)
    for (int idx = tid; idx < 32 * C1; idx += C1)
        whis[idx] = W1[32 * C1 + idx];

    float w00 = W0[c], w01 = W0[C0 + c], w02 = W0[2 * C0 + c], w03 = W0[3 * C0 + c];
    float a0 = g_a0[c], c0 = g_c0[c];

    double dsum = 0.0, dssq = 0.0;
    unsigned h0base_ch = (unsigned)__cvta_generic_to_shared(h0s);
    __syncthreads();

    for (int seg = blockIdx.x; seg < NSEG; seg += gridDim.x) {
        int cnt = g_cnt[seg];
        if (cnt == 0) continue;
        int off = g_off[seg];

        float lmin = INFINITY, lmax = -INFINITY;
        float accmin = INFINITY, accmax = -INFINITY;
        ull sum2 = 0, ssq2 = 0;               // packed (0.0f,0.0f)
        float sumt = 0.0f, ssqt = 0.0f;       // tail scalar

        for (int chunk = 0; chunk < cnt; chunk += 64) {
            int m = min(64, cnt - chunk);
            int m_pad = (m + 3) & ~3;
            // phase A: h0 for points [chunk, chunk+m), channel-major, pad=duplicate last
            for (int p = row; p < m_pad; p += 4) {
                int pi = min(p, m - 1);
                float4 f = g_feat[off + chunk + pi];
                float h = f.x * w00 + f.y * w01 + f.z * w02 + f.w * w03;
                lmin = fminf(lmin, h);
                lmax = fmaxf(lmax, h);
                h0s[c * PAD + p] = swishf(a0 * h + c0);
            }
            __syncthreads();
            // phase B: packed f32x2 dot for 4 points at a time
            for (int g = 0; g < m_pad; g += 4) {
                ull acc01 = 0, acc23 = 0;
                unsigned base = h0base_ch + g * 4;
                bloop<0>(base, wp, acc01, acc23);
                float a0f, a1f, a2f, a3f;
                upk2(acc01, a0f, a1f);
                upk2(acc23, a2f, a3f);
                if (g + 4 <= m) {
                    accmin = fminf(accmin, fminf(fminf(a0f, a1f), fminf(a2f, a3f)));
                    accmax = fmaxf(accmax, fmaxf(fmaxf(a0f, a1f), fmaxf(a2f, a3f)));
                    sum2 = add2(sum2, add2(acc01, acc23));
                    ssq2 = fma2(acc01, acc01, ssq2);
                    ssq2 = fma2(acc23, acc23, ssq2);
                } else {
                    float av[4] = {a0f, a1f, a2f, a3f};
#pragma unroll
                    for (int s = 0; s < 4; s++) {
                        if (g + s < m) {
                            accmin = fminf(accmin, av[s]);
                            accmax = fmaxf(accmax, av[s]);
                            sumt += av[s];
                            ssqt = fmaf(av[s], av[s], ssqt);
                        }
                    }
                }
            }
            __syncthreads();
        }

        // reduce h0_pre range across the 4 warp rows, compute m0
        pm[row][c] = lmin;
        pM[row][c] = lmax;
        __syncthreads();
        if (tid < 32) {
            float mn = fminf(fminf(pm[0][tid], pm[1][tid]), fminf(pm[2][tid], pm[3][tid]));
            float mx = fmaxf(fmaxf(pM[0][tid], pM[1][tid]), fmaxf(pM[2][tid], pM[3][tid]));
            m0s[tid] = swish_seg_max(mn, mx, g_a0[tid], g_c0[tid]);
        }
        __syncthreads();

        // segment-constant part: B = m0 . W1[32:64, tid]  (weights from shared)
        float B = 0.0f;
#pragma unroll
        for (int j = 0; j < 32; j++) B = fmaf(m0s[j], whis[j * C1 + tid], B);

        g_min1[(size_t)seg * C1 + tid] = accmin + B;
        g_max1[(size_t)seg * C1 + tid] = accmax + B;

        float slo, shi, qlo, qhi;
        upk2(sum2, slo, shi);
        upk2(ssq2, qlo, qhi);
        float sum = slo + shi + sumt;
        float ssq = qlo + qhi + ssqt;

        float fc = (float)cnt;
        dsum += (double)(sum + fc * B);
        dssq += (double)(ssq + 2.0f * B * sum + fc * B * B);
        __syncthreads();
    }

    atomicAdd(&g_s1[tid], dsum);
    atomicAdd(&g_ss1[tid], dssq);
}

// ---------------- S1: bn1 affine ----------------
__global__ void k_s1(const float* __restrict__ g1, const float* __restrict__ b1, int N) {
    int ch = threadIdx.x;
    if (ch >= C1) return;
    double dN = (double)N;
    double mu = g_s1[ch] / dN;
    double var = g_ss1[ch] / dN - mu * mu;
    double a = (double)g1[ch] / sqrt(var + (double)EPSB);
    g_a1[ch] = (float)a;
    g_c1[ch] = (float)((double)b1[ch] - mu * a);
}

// ---------------- T2: resolve m1, scatter into dense (B, C, GY, GX) ----------------
__global__ void k_t2() {
    int i = blockIdx.x * blockDim.x + threadIdx.x;
    if (i >= NSEG * C1) return;
    int ch = i & (C1 - 1);
    int seg = i >> 7;
    float val = 0.0f;
    if (g_cnt[seg] > 0) {
        float a = g_a1[ch], c = g_c1[ch];
        float pmin = g_min1[i], pmax = g_max1[i];
        if (a < 0.0f) { float tmp = pmin; pmin = pmax; pmax = tmp; }
        val = fmaxf(swishf(a * pmin + c), swishf(a * pmax + c));
    }
    int cy = seg % GY;
    int r = seg / GY;
    int cx = r % GX;
    int b = r / GX;
    g_dense[((b * C1 + ch) * GY + cy) * GX + cx] = val;
}

// ---------------- R: bilinear resize (align-corners linspace) ----------------
__global__ void k_resize(float* __restrict__ out, int total) {
    int i = blockIdx.x * blockDim.x + threadIdx.x;
    if (i >= total) return;
    int xo = i % 224;
    int yo = (i / 224) % 224;
    int bc = i / (224 * 224);

    const float sy = (GY - 1.0f) / 223.0f;
    const float sx = (GX - 1.0f) / 223.0f;
    float yy = (float)yo * sy;
    float xx = (float)xo * sx;
    int y0 = (int)floorf(yy);
    int x0 = (int)floorf(xx);
    int y1 = min(y0 + 1, GY - 1);
    int x1 = min(x0 + 1, GX - 1);
    float wy = yy - (float)y0;
    float wx = xx - (float)x0;

    const float* d = g_dense + (size_t)bc * GY * GX;
    float d00 = d[y0 * GX + x0];
    float d01 = d[y0 * GX + x1];
    float d10 = d[y1 * GX + x0];
    float d11 = d[y1 * GX + x1];
    float xh0 = d00 * (1.0f - wy) + d10 * wy;
    float xh1 = d01 * (1.0f - wy) + d11 * wy;
    out[i] = xh0 * (1.0f - wx) + xh1 * wx;
}

// ---------------- launch ----------------
extern "C" void kernel_launch(void* const* d_in, const int* in_sizes, int n_in,
                              void* d_out, int out_size) {
    const float* pts = (const float*)d_in[1];
    const float* W0  = (const float*)d_in[2];
    const float* g0  = (const float*)d_in[3];
    const float* b0  = (const float*)d_in[4];
    const float* W1  = (const float*)d_in[5];
    const float* g1  = (const float*)d_in[6];
    const float* b1  = (const float*)d_in[7];
    float* out = (float*)d_out;
    int N = in_sizes[1] / 5;
    if (N > MAXN) N = MAXN;

    k_init<<<(NSEG + 255) / 256, 256>>>();
    k_p1<<<(N + 255) / 256, 256>>>(pts, N);
    k_scan<<<1, 1024>>>();
    k_s0<<<1, 32>>>(W0, g0, b0, N);
    k_scatter<<<(N + 255) / 256, 256>>>(pts, N);
    k_seg<<<NBLK, C1>>>(W0, W1);
    k_s1<<<1, C1>>>(g1, b1, N);
    k_t2<<<(NSEG * C1 + 255) / 256, 256>>>();
    k_resize<<<(out_size + 255) / 256, 256>>>(out, out_size);
}